// round 17
// baseline (speedup 1.0000x reference)
#include <cuda_runtime.h>
#include <cstdint>

#define B_SZ  8
#define SEQ   4096
#define HID   1024
#define HID2  (HID / 2)
#define HID4  (HID / 4)
#define DMAX  16             // FIR truncation: g[d] <= 0.64*0.16^d -> 4e-13 at d=16
#define CHUNKS 16            // time-chunks; block = (b, chunk) covers full h-row
#define CGRP   8             // stored 32-step groups per chunk
#define WGRP   6             // warmup groups (192 steps): 0.9^192 ~ 1.7e-9

// ---------------- LIF step: float-mask form (masks exactly 0.0/1.0) --------------
struct SnnState { float w09, ns, act, r; };

__device__ __forceinline__ void snn_step(SnnState& st, float xk,
                                         float& macc, float mc)
{
    float v1 = __fmaf_rn(st.w09, st.ns, xk);          // rn(0.9*v_post + x)
    float ge; asm("set.ge.f32.f32 %0, %1, %2;" : "=f"(ge) : "f"(v1), "f"(1.0f));
    float s  = __fmul_rn(ge, st.act);                 // spike as 0.0/1.0
    st.w09   = __fmul_rn(v1, 0.9f);
    st.ns    = __fmaf_rn(-ge, st.act, 1.0f);          // 1 - spike (exact)
    float rd = fmaxf(__fadd_rn(st.r, -1.0f), 0.0f);   // max(r-1,0), exact
    st.r     = __fmaf_rn(s, 5.0f, rd);                // spike => rd==0 => 5
    asm("set.le.f32.f32 %0, %1, %2;" : "=f"(st.act) : "f"(st.r), "f"(0.0f));
    macc     = __fmaf_rn(s, mc, macc);                // exact bit accumulation
}

// 32x32 bit-matrix transpose across a warp (Hacker's Delight butterfly).
// Output: lane L's word has popc == column-sum for time (31 - L).
__device__ __forceinline__ unsigned bit_transpose32(unsigned x, int lane)
{
    unsigned m = 0x0000FFFFu;
    #pragma unroll
    for (int j = 16; j; j >>= 1) {
        unsigned y  = __shfl_xor_sync(0xffffffffu, x, j);
        unsigned lm = (lane & j) ? (m << j) : m;
        unsigned yy = (lane & j) ? (y << j) : (y >> j);
        x ^= (x ^ yy) & lm;
        m ^= m << (j >> 1);     // constant-folded under full unroll
    }
    return x;
}

// ---------------- single fused kernel, PHASE-SPLIT --------------------------------
// 128 blocks x 512 threads: block = (b, chunk) owns the full 1024-h row.
//  P1: barrier-free scan of all groups; masks (32KB) + u-partials (18KB) -> smem
//  B1 -> u_all[288] (32-halo + 256)  B2 -> y FIR (256 t parallel)  B3
//  P3: stream 1 MB of output from smem masks + y.
__global__ void __launch_bounds__(512) fused_kernel(const float* __restrict__ x,
                                                    const float* __restrict__ Ap,
                                                    const float* __restrict__ Bp,
                                                    const float* __restrict__ Cp,
                                                    const float* __restrict__ Dp,
                                                    float* __restrict__ out)
{
    __shared__ float As[64 * 65];        // A rows padded (g prologue)
    __shared__ float Wall[DMAX][64];     // Krylov vectors A^d B
    __shared__ float wping[2][64];
    __shared__ float cs[64];
    __shared__ float g_s[DMAX];
    __shared__ unsigned wsm[CGRP][HID];  // ALL stored group masks (32 KB)
    __shared__ int   part[CGRP + 1][16 * 32];  // u partials: halo + 8 groups
    __shared__ float u_all[32 + CGRP * 32];    // halo(32) + stored u (256)
    __shared__ float y_s[CGRP * 32], y1_s[CGRP * 32];

    const int blk  = blockIdx.x;         // 0..127
    const int c    = blk & (CHUNKS - 1);
    const int b    = blk >> 4;
    const int tid  = threadIdx.x;        // 0..511
    const int wid  = tid >> 5, lane = tid & 31;
    const int h    = tid * 2;            // 2 hidden lanes per thread

    const int warm    = c ? WGRP : 0;
    const int g0      = c * CGRP;
    const int tbegin  = (g0 - warm) * 32;
    const int ngroups = warm + CGRP;     // 8 or 14

    const float2* xp = (const float2*)(x + ((size_t)b * SEQ + tbegin) * HID) + tid;
    float4* out4 = (float4*)(out + ((size_t)b * SEQ + g0 * 32) * HID);
    const float Ds = __ldg(Dp);

    // issue the x prefetch FIRST so DRAM ramps under the g prologue.
    float2 buf[32];
    #pragma unroll
    for (int i = 0; i < 32; i++) buf[i] = xp[(size_t)i * HID2];
    const float2* xld = xp + (size_t)32 * HID2;

    // ---- g prologue: W_0=B; W_d=A W_{d-1}; g[d]=C.W_d ---------------------------
    for (int i = tid; i < 64 * 64; i += 512)
        As[(i >> 6) * 65 + (i & 63)] = Ap[i];
    if (tid < 64) {
        cs[tid] = Cp[tid];
        float b0 = Bp[tid];
        wping[0][tid] = b0;
        Wall[0][tid]  = b0;
    }
    if (c == 0) part[0][tid] = 0;        // halo partials = 0 for chunk 0
    __syncthreads();
    {
        const int row = tid >> 3, sub = tid & 7;         // 8 threads per row
        for (int d = 1; d < DMAX; d++) {
            const float* wprev = wping[(d - 1) & 1];
            float p = 0.f;
            #pragma unroll
            for (int j = 0; j < 8; j++)
                p += As[row * 65 + sub * 8 + j] * wprev[sub * 8 + j];
            p += __shfl_xor_sync(0xffffffffu, p, 1);
            p += __shfl_xor_sync(0xffffffffu, p, 2);
            p += __shfl_xor_sync(0xffffffffu, p, 4);
            if (sub == 0) { wping[d & 1][row] = p; Wall[d][row] = p; }
            __syncthreads();
        }
        if (tid < DMAX * 8) {                            // all 16 dots in parallel
            const int d = tid >> 3, s8 = (tid & 7) * 8;
            float p = 0.f;
            #pragma unroll
            for (int j = 0; j < 8; j++) p += cs[s8 + j] * Wall[d][s8 + j];
            p += __shfl_xor_sync(0xffffffffu, p, 1);
            p += __shfl_xor_sync(0xffffffffu, p, 2);
            p += __shfl_xor_sync(0xffffffffu, p, 4);
            if ((tid & 7) == 0) g_s[d] = p;
        }
    }
    // (no barrier needed here: g_s is first read after B1)

    // ---- PHASE 1: barrier-free scan of all groups --------------------------------
    SnnState s0 = {0,1,1,0}, s1 = {0,1,1,0};

    for (int gg = 0; gg < ngroups; gg++) {
        const bool pf = (gg + 1 < ngroups);
        float m0l = 0, m0h = 0, m1l = 0, m1h = 0;
        #pragma unroll
        for (int i = 0; i < 32; i++) {
            float2 xk = buf[i];
            if (pf) buf[i] = xld[(size_t)i * HID2];      // prefetch next group
            const float mc = (float)(1u << (i & 15));
            if (i < 16) { snn_step(s0, xk.x, m0l, mc); snn_step(s1, xk.y, m1l, mc); }
            else        { snn_step(s0, xk.x, m0h, mc); snn_step(s1, xk.y, m1h, mc); }
        }
        xld += (size_t)32 * HID2;

        const int pi = gg - warm + 1;                    // partials slot (0 = halo)
        if (pi < 0) continue;                            // uniform per block

        uint2 mv;
        mv.x = __float2uint_rn(m0l) | (__float2uint_rn(m0h) << 16);
        mv.y = __float2uint_rn(m1l) | (__float2uint_rn(m1h) << 16);
        unsigned tx = bit_transpose32(mv.x, lane);
        unsigned ty = bit_transpose32(mv.y, lane);
        part[pi][wid * 32 + (31 ^ lane)] = __popc(tx) + __popc(ty);
        if (gg >= warm) *(uint2*)&wsm[gg - warm][h] = mv;
    }
    __syncthreads();                                     // B1: masks + partials

    // ---- u: 288 values (32 halo + 256 stored) -------------------------------------
    if (tid < 32 + CGRP * 32) {
        const int pj = tid >> 5, tt = tid & 31;
        const int* pb = part[pj];
        int tot = 0;
        #pragma unroll
        for (int w2 = 0; w2 < 16; w2++) tot += pb[w2 * 32 + tt];
        u_all[tid] = (float)tot * (1.0f / (float)HID);
    }
    __syncthreads();                                     // B2: u_all ready

    // ---- y = D*u + g (*) u for all 256 stored t -----------------------------------
    if (tid < CGRP * 32) {
        float acc = Ds * u_all[32 + tid];
        #pragma unroll
        for (int d = 0; d < DMAX; d++)
            acc += g_s[d] * u_all[32 + tid - d];
        y_s[tid]  = acc;
        y1_s[tid] = acc + 1.0f;
    }
    __syncthreads();                                     // B3: y ready

    // ---- PHASE 3: stream output from smem masks + y -------------------------------
    const int q  = tid & 255;
    const int hf = tid >> 8;
    #pragma unroll
    for (int grp = 0; grp < CGRP; grp++) {
        const uint4 w4 = ((const uint4*)wsm[grp])[q];
        float4* rowb = out4 + (size_t)grp * 32 * HID4 + q;
        #pragma unroll
        for (int k = 0; k < 16; k++) {
            const int t = hf * 16 + k;
            const float y = y_s[grp * 32 + t], y1 = y1_s[grp * 32 + t];
            float4 o;
            o.x = ((w4.x >> t) & 1u) ? y1 : y;
            o.y = ((w4.y >> t) & 1u) ? y1 : y;
            o.z = ((w4.z >> t) & 1u) ? y1 : y;
            o.w = ((w4.w >> t) & 1u) ? y1 : y;
            __stcs(&rowb[(size_t)t * HID4], o);
        }
    }
}

// ---------------- launch ----------------------------------------------------------
extern "C" void kernel_launch(void* const* d_in, const int* in_sizes, int n_in,
                              void* d_out, int out_size)
{
    const float* x  = (const float*)d_in[0];   // (8, 4096, 1024) f32
    const float* A  = (const float*)d_in[1];   // (64, 64)
    const float* Bv = (const float*)d_in[2];   // (64, 1)
    const float* Cv = (const float*)d_in[3];   // (1, 64)
    const float* Dp = (const float*)d_in[4];   // (1, 1)

    fused_kernel<<<B_SZ * CHUNKS, 512>>>(x, A, Bv, Cv, Dp, (float*)d_out);
}